// round 1
// baseline (speedup 1.0000x reference)
#include <cuda_runtime.h>
#include <math.h>

#define B_   4
#define S_   2048
#define DIN  512
#define U_   64
#define WIN_ 32
#define L_OUT 132064   // sum of window lengths

// ---------------- scratch (no allocations allowed) ----------------
__device__ float g_Q[B_ * S_ * U_];
__device__ float g_K[B_ * S_ * U_];
__device__ float g_V[B_ * S_ * U_];

// ======================= Kernel A: QKV projections =======================
// out[p] (8192 x 64) = X @ W[p] + b[p], X = query (p=0) or value (p=1,2)
// Block: 128 threads, tile 64(M) x 64(N), K-chunks of 64.
__global__ void proj_kernel(const float* __restrict__ query,
                            const float* __restrict__ value,
                            const float* __restrict__ Wq, const float* __restrict__ bq,
                            const float* __restrict__ Wk, const float* __restrict__ bk,
                            const float* __restrict__ Wv, const float* __restrict__ bv)
{
    const int p = blockIdx.y;
    const float* X  = (p == 0) ? query : value;
    const float* Wm = (p == 0) ? Wq : ((p == 1) ? Wk : Wv);
    const float* bm = (p == 0) ? bq : ((p == 1) ? bk : bv);
    float* O        = (p == 0) ? g_Q : ((p == 1) ? g_K : g_V);

    const int m0 = blockIdx.x * 64;

    __shared__ float Ast[64 * 68];  // [k][m], transposed A tile, pad 68
    __shared__ float Bs [64 * 68];  // [k][n], pad 68

    const int tid = threadIdx.x;       // 0..127
    const int tx  = tid & 15;          // n-group (4 cols each)
    const int ty  = tid >> 4;          // m-group (8 rows each), 0..7

    float acc[8][4];
    #pragma unroll
    for (int i = 0; i < 8; ++i)
        #pragma unroll
        for (int j = 0; j < 4; ++j) acc[i][j] = 0.f;

    const int r  = tid >> 4;           // 0..7
    const int c4 = (tid & 15) * 4;     // 0..60

    for (int k0 = 0; k0 < DIN; k0 += 64) {
        // load A tile (64 rows x 64 k), transpose into Ast[k][m]
        #pragma unroll
        for (int it = 0; it < 8; ++it) {
            const int m = r + it * 8;
            float4 v = *(const float4*)&X[(size_t)(m0 + m) * DIN + k0 + c4];
            Ast[(c4 + 0) * 68 + m] = v.x;
            Ast[(c4 + 1) * 68 + m] = v.y;
            Ast[(c4 + 2) * 68 + m] = v.z;
            Ast[(c4 + 3) * 68 + m] = v.w;
        }
        // load B tile (64 k x 64 n)
        #pragma unroll
        for (int it = 0; it < 8; ++it) {
            const int kk = r + it * 8;
            float4 v = *(const float4*)&Wm[(size_t)(k0 + kk) * U_ + c4];
            *(float4*)&Bs[kk * 68 + c4] = v;
        }
        __syncthreads();

        #pragma unroll 8
        for (int k = 0; k < 64; ++k) {
            float4 a0 = *(float4*)&Ast[k * 68 + ty * 8];
            float4 a1 = *(float4*)&Ast[k * 68 + ty * 8 + 4];
            float4 bf = *(float4*)&Bs [k * 68 + tx * 4];
            float am[8] = {a0.x, a0.y, a0.z, a0.w, a1.x, a1.y, a1.z, a1.w};
            float bn[4] = {bf.x, bf.y, bf.z, bf.w};
            #pragma unroll
            for (int i = 0; i < 8; ++i)
                #pragma unroll
                for (int j = 0; j < 4; ++j)
                    acc[i][j] += am[i] * bn[j];
        }
        __syncthreads();
    }

    float4 bias = *(const float4*)&bm[tx * 4];
    #pragma unroll
    for (int i = 0; i < 8; ++i) {
        float4 o;
        o.x = acc[i][0] + bias.x;
        o.y = acc[i][1] + bias.y;
        o.z = acc[i][2] + bias.z;
        o.w = acc[i][3] + bias.w;
        *(float4*)&O[(size_t)(m0 + ty * 8 + i) * U_ + tx * 4] = o;
    }
}

// ======================= Kernel B: banded attention =======================
// For each query position j: band scores sc(j,u)=Q[j].K[u], u in [j-64, j+64];
// e = exp(sc - band_max). For each center s containing j, the softmax over
// window(s) is a sliding window sum over u -> O(1) update per center.
// One warp per j; block handles TJ=16 consecutive j for one batch.

#define TJ   16
#define NB   (TJ + 128)       // 144 band rows in smem
#define KTS  177              // Kt column stride (odd mult -> conflict-free)

__device__ __forceinline__ int off_of(int s)
{
    // offsets = exclusive prefix sum of window lengths
    if (s <= 32)   return s * 33 + (s * (s - 1)) / 2;
    if (s <= 2016) return 1552 + (s - 32) * 65;
    return 130512 + ((2145 - s) * (s - 2016)) / 2;
}

extern __shared__ float sm_b[];

__global__ void attn_kernel(float* __restrict__ out)
{
    float* Kt = sm_b;                 // [64][KTS]  (transposed K band)
    float* Vs = Kt + 64 * KTS;        // [NB][64]
    float* Qs = Vs + NB * 64;         // [TJ][64]
    float* Es = Qs + TJ * 64;         // [TJ][132]  (e values per j, idx 0..128)

    const int b   = blockIdx.y;
    const int j0  = blockIdx.x * TJ;
    const int tid = threadIdx.x;      // 512 threads
    const int ubase = j0 - 64;

    // ---- load tiles ----
    for (int idx = tid; idx < TJ * U_; idx += 512)
        Qs[idx] = g_Q[((size_t)b * S_ + j0) * U_ + idx];

    for (int idx = tid; idx < NB * U_; idx += 512) {
        const int ug = idx >> 6, d = idx & 63;
        const int u = ubase + ug;
        if (u >= 0 && u < S_)
            Vs[idx] = g_V[((size_t)b * S_ + u) * U_ + d];
    }
    for (int idx = tid; idx < NB * U_; idx += 512) {
        const int ug = idx >> 6, d = idx & 63;
        const int u = ubase + ug;
        if (u >= 0 && u < S_)
            Kt[d * KTS + ug] = g_K[((size_t)b * S_ + u) * U_ + d];
    }
    __syncthreads();

    const int wj   = tid >> 5;        // warp id = local j
    const int lane = tid & 31;
    const int j    = j0 + wj;

    // ---- phase 1: band scores + exp ----
    float a0 = 0.f, a1 = 0.f, a2 = 0.f, a3 = 0.f, a4 = 0.f;
    {
        const float* kt = Kt + wj + lane;
        const float* qp = Qs + wj * U_;
        #pragma unroll 16
        for (int d = 0; d < 64; ++d) {
            const float qd = qp[d];
            const float* kr = kt + d * KTS;
            a0 += qd * kr[0];
            a1 += qd * kr[32];
            a2 += qd * kr[64];
            a3 += qd * kr[96];
            a4 += qd * kr[128];
        }
    }
    const float NEG_INF = __int_as_float(0xff800000);
    const float scale = 0.125f;       // 1/sqrt(64)
    float sc[5] = {a0 * scale, a1 * scale, a2 * scale, a3 * scale, a4 * scale};
    float m = NEG_INF;
    #pragma unroll
    for (int k = 0; k < 5; ++k) {
        const int uu = lane + 32 * k;
        const int u  = j - 64 + uu;
        const bool valid = (uu <= 128) && (u >= 0) && (u < S_);
        sc[k] = valid ? sc[k] : NEG_INF;
        m = fmaxf(m, sc[k]);
    }
    #pragma unroll
    for (int off = 16; off > 0; off >>= 1)
        m = fmaxf(m, __shfl_xor_sync(0xffffffffu, m, off));
    #pragma unroll
    for (int k = 0; k < 5; ++k) {
        const int uu = lane + 32 * k;
        if (uu <= 128)
            Es[wj * 132 + uu] = __expf(sc[k] - m);   // -inf -> 0
    }
    __syncwarp();

    // ---- phase 2: sliding window sums over centers s containing j ----
    const int smin = (j - 32 > 0) ? (j - 32) : 0;
    const int smax = (j + 32 < S_ - 1) ? (j + 32) : (S_ - 1);

    const float* ej = Es + wj * 132;
    const int ebase = j - 64;

    // init at s = smin
    float n0 = 0.f, n1 = 0.f, Dv = 0.f;
    {
        const int st = (smin - 32 > 0) ? (smin - 32) : 0;
        const int en = (smin + 33 < S_) ? (smin + 33) : S_;
        for (int u = st; u < en; ++u) {
            const float e = ej[u - ebase];
            const float2 v = *(const float2*)&Vs[(u - ubase) * U_ + 2 * lane];
            Dv += e; n0 += e * v.x; n1 += e * v.y;
        }
    }

    const size_t outbase = (size_t)b * L_OUT * U_;
    for (int s = smin; ; ++s) {
        const int startS = (s - 32 > 0) ? (s - 32) : 0;
        const int row = off_of(s) + (j - startS);
        const float invD = __fdividef(1.0f, Dv);
        float2 o;
        o.x = n0 * invD;
        o.y = n1 * invD;
        *(float2*)&out[outbase + (size_t)row * U_ + 2 * lane] = o;

        if (s == smax) break;

        if (s >= 32) {                      // window start advances
            const int u = s - 32;
            const float e = ej[u - ebase];
            const float2 v = *(const float2*)&Vs[(u - ubase) * U_ + 2 * lane];
            Dv -= e; n0 -= e * v.x; n1 -= e * v.y;
        }
        if (s + 33 < S_) {                  // window end advances
            const int u = s + 33;
            const float e = ej[u - ebase];
            const float2 v = *(const float2*)&Vs[(u - ubase) * U_ + 2 * lane];
            Dv += e; n0 += e * v.x; n1 += e * v.y;
        }
    }
}

// ======================= launch =======================
extern "C" void kernel_launch(void* const* d_in, const int* in_sizes, int n_in,
                              void* d_out, int out_size)
{
    const float* query = (const float*)d_in[0];
    const float* value = (const float*)d_in[1];
    const float* Wq    = (const float*)d_in[2];
    const float* bq    = (const float*)d_in[3];
    const float* Wk    = (const float*)d_in[4];
    const float* bk    = (const float*)d_in[5];
    const float* Wv    = (const float*)d_in[6];
    const float* bv    = (const float*)d_in[7];
    float* out = (float*)d_out;

    dim3 gA((B_ * S_) / 64, 3);
    proj_kernel<<<gA, 128>>>(query, value, Wq, bq, Wk, bk, Wv, bv);

    const int smem_bytes = (64 * KTS + NB * U_ + TJ * U_ + TJ * 132) * (int)sizeof(float);
    cudaFuncSetAttribute(attn_kernel, cudaFuncAttributeMaxDynamicSharedMemorySize, smem_bytes);
    dim3 gB(S_ / TJ, B_);
    attn_kernel<<<gB, 512, smem_bytes>>>(out);
}

// round 5
// speedup vs baseline: 1.3398x; 1.3398x over previous
#include <cuda_runtime.h>
#include <math.h>

#define B_   4
#define S_   2048
#define DIN  512
#define U_   64
#define L_OUT 132064

typedef unsigned long long ull;

// ---------------- f32x2 packed helpers (sm_103a) ----------------
__device__ __forceinline__ ull dup2(float x) {
    ull r; asm("mov.b64 %0, {%1, %1};" : "=l"(r) : "f"(x)); return r;
}
__device__ __forceinline__ void fma2(ull &d, ull a, ull b) {
    asm("fma.rn.f32x2 %0, %1, %2, %3;" : "=l"(d) : "l"(a), "l"(b), "l"(d));
}
__device__ __forceinline__ ull mul2(ull a, ull b) {
    ull d; asm("mul.rn.f32x2 %0, %1, %2;" : "=l"(d) : "l"(a), "l"(b)); return d;
}
__device__ __forceinline__ float2 unpk(ull v) {
    float2 f; asm("mov.b64 {%0, %1}, %2;" : "=f"(f.x), "=f"(f.y) : "l"(v)); return f;
}

// ---------------- scratch ----------------
__device__ float g_Q[B_ * S_ * U_];
__device__ float g_K[B_ * S_ * U_];
__device__ float g_V[B_ * S_ * U_];

// ======================= Kernel A: QKV projections (f32x2) =======================
// Tile M=64, N=64, 128 threads, per-thread 8m(4 pairs) x 4n. K-chunk 64.
__global__ __launch_bounds__(128, 4)
void proj_kernel(const float* __restrict__ query,
                 const float* __restrict__ value,
                 const float* __restrict__ Wq, const float* __restrict__ bq,
                 const float* __restrict__ Wk, const float* __restrict__ bk,
                 const float* __restrict__ Wv, const float* __restrict__ bv)
{
    const int p = blockIdx.y;
    const float* X  = (p == 0) ? query : value;
    const float* Wm = (p == 0) ? Wq : ((p == 1) ? Wk : Wv);
    const float* bm = (p == 0) ? bq : ((p == 1) ? bk : bv);
    float* O        = (p == 0) ? g_Q : ((p == 1) ? g_K : g_V);

    const int m0 = blockIdx.x * 64;

    __shared__ float Ast[64][68];   // [k][m]  (transposed A tile)
    __shared__ float Bs [64][68];   // [k][n]

    const int tid = threadIdx.x;
    const int tx  = tid & 15;       // n-group: cols tx*4 .. tx*4+3
    const int tym = tid >> 4;       // m-group: rows tym*8 .. tym*8+7

    ull acc2[4][4];
    #pragma unroll
    for (int i = 0; i < 4; ++i)
        #pragma unroll
        for (int j = 0; j < 4; ++j) acc2[i][j] = 0ull;

    const int r  = tid >> 4;        // 0..7
    const int c4 = (tid & 15) * 4;  // 0..60

    for (int k0 = 0; k0 < DIN; k0 += 64) {
        // A tile: 64m x 64k, transpose into Ast[k][m]
        #pragma unroll
        for (int it = 0; it < 8; ++it) {
            const int m = r + it * 8;
            float4 v = *(const float4*)&X[(size_t)(m0 + m) * DIN + k0 + c4];
            Ast[c4 + 0][m] = v.x;
            Ast[c4 + 1][m] = v.y;
            Ast[c4 + 2][m] = v.z;
            Ast[c4 + 3][m] = v.w;
        }
        // B tile: 64k x 64n
        #pragma unroll
        for (int it = 0; it < 8; ++it) {
            const int kk = r + it * 8;
            *(float4*)&Bs[kk][c4] = *(const float4*)&Wm[(size_t)(k0 + kk) * U_ + c4];
        }
        __syncthreads();

        #pragma unroll 8
        for (int k = 0; k < 64; ++k) {
            ulonglong2 aA = *(const ulonglong2*)&Ast[k][tym * 8];
            ulonglong2 aB = *(const ulonglong2*)&Ast[k][tym * 8 + 4];
            float4 bf = *(const float4*)&Bs[k][tx * 4];
            ull b0 = dup2(bf.x), b1 = dup2(bf.y), b2 = dup2(bf.z), b3 = dup2(bf.w);
            fma2(acc2[0][0], aA.x, b0); fma2(acc2[0][1], aA.x, b1);
            fma2(acc2[0][2], aA.x, b2); fma2(acc2[0][3], aA.x, b3);
            fma2(acc2[1][0], aA.y, b0); fma2(acc2[1][1], aA.y, b1);
            fma2(acc2[1][2], aA.y, b2); fma2(acc2[1][3], aA.y, b3);
            fma2(acc2[2][0], aB.x, b0); fma2(acc2[2][1], aB.x, b1);
            fma2(acc2[2][2], aB.x, b2); fma2(acc2[2][3], aB.x, b3);
            fma2(acc2[3][0], aB.y, b0); fma2(acc2[3][1], aB.y, b1);
            fma2(acc2[3][2], aB.y, b2); fma2(acc2[3][3], aB.y, b3);
        }
        __syncthreads();
    }

    float4 bias = *(const float4*)&bm[tx * 4];
    #pragma unroll
    for (int mp = 0; mp < 4; ++mp) {
        float2 e0 = unpk(acc2[mp][0]);
        float2 e1 = unpk(acc2[mp][1]);
        float2 e2 = unpk(acc2[mp][2]);
        float2 e3 = unpk(acc2[mp][3]);
        const int gm = m0 + tym * 8 + 2 * mp;
        float4 lo = {e0.x + bias.x, e1.x + bias.y, e2.x + bias.z, e3.x + bias.w};
        float4 hi = {e0.y + bias.x, e1.y + bias.y, e2.y + bias.z, e3.y + bias.w};
        *(float4*)&O[(size_t)gm * U_ + tx * 4]       = lo;
        *(float4*)&O[(size_t)(gm + 1) * U_ + tx * 4] = hi;
    }
}

// ======================= Kernel B: banded attention =======================
#define TJ   16
#define NB   (TJ + 128)     // 144 band rows
#define KP   68             // padded K row (floats)

__device__ __forceinline__ int off_of(int s)
{
    if (s <= 32)   return s * 33 + (s * (s - 1)) / 2;
    if (s <= 2016) return 1552 + (s - 32) * 65;
    return 130512 + ((2145 - s) * (s - 2016)) / 2;
}

extern __shared__ float sm_b[];

__global__ __launch_bounds__(512, 2)
void attn_kernel(float* __restrict__ out)
{
    float* Ks = sm_b;                 // [NB][KP]   row-major K band (padded)
    float* Vs = Ks + NB * KP;         // [NB][64]
    float* Qs = Vs + NB * 64;         // [TJ][64]
    float* Es = Qs + TJ * 64;         // [TJ][132]

    const int b     = blockIdx.y;
    const int j0    = blockIdx.x * TJ;
    const int tid   = threadIdx.x;    // 512
    const int ubase = j0 - 64;

    // ---- tile loads (clamped, vectorized) ----
    {
        const size_t gbase = (size_t)b * S_ * U_;
        for (int i = tid; i < TJ * 16; i += 512) {
            *(float4*)&Qs[i * 4] = *(const float4*)&g_Q[gbase + (size_t)j0 * U_ + i * 4];
        }
        for (int i = tid; i < NB * 16; i += 512) {
            const int ug = i >> 4, d4 = (i & 15) << 2;
            int u = ubase + ug;
            u = (u < 0) ? 0 : ((u > S_ - 1) ? S_ - 1 : u);
            const float4 kv = *(const float4*)&g_K[gbase + (size_t)u * U_ + d4];
            const float4 vv = *(const float4*)&g_V[gbase + (size_t)u * U_ + d4];
            *(float4*)&Ks[ug * KP + d4] = kv;
            *(float4*)&Vs[ug * 64 + d4] = vv;
        }
    }
    __syncthreads();

    const int wj   = tid >> 5;
    const int lane = tid & 31;
    const int j    = j0 + wj;

    // ---- phase 1: band scores (f32x2 pairs along d) ----
    {
        const float* qrow  = Qs + wj * 64;
        const float* kbase = Ks + (wj + lane) * KP;
        ull acc[5][2];
        #pragma unroll
        for (int k5 = 0; k5 < 5; ++k5) { acc[k5][0] = 0ull; acc[k5][1] = 0ull; }

        #pragma unroll
        for (int d = 0; d < 64; d += 4) {
            ulonglong2 q = *(const ulonglong2*)&qrow[d];
            #pragma unroll
            for (int k5 = 0; k5 < 5; ++k5) {
                ulonglong2 kv = *(const ulonglong2*)&kbase[k5 * 32 * KP + d];
                fma2(acc[k5][0], q.x, kv.x);
                fma2(acc[k5][1], q.y, kv.y);
            }
        }

        const float NEG_INF = __int_as_float(0xff800000);
        const float scale = 0.125f;
        float sc[5], m = NEG_INF;
        #pragma unroll
        for (int k5 = 0; k5 < 5; ++k5) {
            float2 lo = unpk(acc[k5][0]);
            float2 hi = unpk(acc[k5][1]);
            sc[k5] = ((lo.x + lo.y) + (hi.x + hi.y)) * scale;
            const int uu = lane + 32 * k5;
            const int u  = j - 64 + uu;
            const bool valid = (uu <= 128) && (u >= 0) && (u < S_);
            sc[k5] = valid ? sc[k5] : NEG_INF;
            m = fmaxf(m, sc[k5]);
        }
        #pragma unroll
        for (int off = 16; off > 0; off >>= 1)
            m = fmaxf(m, __shfl_xor_sync(0xffffffffu, m, off));
        #pragma unroll
        for (int k5 = 0; k5 < 5; ++k5) {
            const int uu = lane + 32 * k5;
            if (uu <= 128)
                Es[wj * 132 + uu] = __expf(sc[k5] - m);
        }
    }
    __syncwarp();

    // ---- phase 2: branch-free segmented sliding-window sums ----
    const int smin = (j - 32 > 0) ? (j - 32) : 0;
    const int smax = (j + 32 < S_ - 1) ? (j + 32) : (S_ - 1);
    const float* ej = Es + wj * 132;
    const int ebase = j - 64;

    float Dv = 0.f; ull n = 0ull;
    {   // init window at s = smin
        const int st = (smin - 32 > 0) ? (smin - 32) : 0;
        const int en = (smin + 33 < S_) ? (smin + 33) : S_;
        const float* pe = ej + (st - ebase);
        const float* pv = Vs + (st - ubase) * 64 + 2 * lane;
        for (int u = st; u < en; ++u) {
            const float e = *pe++;
            const ull v = *(const ull*)pv; pv += 64;
            fma2(n, dup2(e), v);
            Dv += e;
        }
    }

    const int st0 = (smin - 32 > 0) ? (smin - 32) : 0;
    float* po = out + (size_t)b * L_OUT * U_
                    + ((size_t)off_of(smin) + (j - st0)) * U_ + 2 * lane;
    const float* pe_add = ej + (smin + 33 - ebase);
    const float* pv_add = Vs + (smin + 33 - ubase) * 64 + 2 * lane;

    // segment 1: growing windows (s <= 31), add-only
    const int e1 = (smax < 31) ? smax : 31;
    for (int s = smin; s <= e1; ++s) {
        const float invD = __fdividef(1.f, Dv);
        *(ull*)po = mul2(n, dup2(invD));
        po += (size_t)(s + 33) * U_;
        const float ea = *pe_add++;
        const ull va = *(const ull*)pv_add; pv_add += 64;
        fma2(n, dup2(ea), va);
        Dv += ea;
    }

    // segment 2: steady state, both updates, row += 64
    const int s2a = (smin > 32) ? smin : 32;
    const int s2b = (smax < 2014) ? smax : 2014;
    const float* pe_sub = ej + (s2a - 32 - ebase);
    const float* pv_sub = Vs + (s2a - 32 - ubase) * 64 + 2 * lane;
    #pragma unroll 2
    for (int s = s2a; s <= s2b; ++s) {
        const float invD = __fdividef(1.f, Dv);
        *(ull*)po = mul2(n, dup2(invD));
        po += 64 * U_;
        const float es = *pe_sub++;
        const float ea = *pe_add++;
        const ull vs_ = *(const ull*)pv_sub; pv_sub += 64;
        const ull va_ = *(const ull*)pv_add; pv_add += 64;
        fma2(n, dup2(ea), va_);
        const float nes = -es;
        fma2(n, dup2(nes), vs_);
        Dv += (ea - es);
    }

    // segment 3: shrinking windows (s >= 2015), sub-only
    const int s3a = (smin > 2015) ? smin : 2015;
    for (int s = s3a; s <= smax; ++s) {
        const float invD = __fdividef(1.f, Dv);
        *(ull*)po = mul2(n, dup2(invD));
        po += (size_t)(2079 - s) * U_;
        const float es = *pe_sub++;
        const ull vs_ = *(const ull*)pv_sub; pv_sub += 64;
        const float nes = -es;
        fma2(n, dup2(nes), vs_);
        Dv -= es;
    }
}

// ======================= launch =======================
extern "C" void kernel_launch(void* const* d_in, const int* in_sizes, int n_in,
                              void* d_out, int out_size)
{
    const float* query = (const float*)d_in[0];
    const float* value = (const float*)d_in[1];
    const float* Wq    = (const float*)d_in[2];
    const float* bq    = (const float*)d_in[3];
    const float* Wk    = (const float*)d_in[4];
    const float* bk    = (const float*)d_in[5];
    const float* Wv    = (const float*)d_in[6];
    const float* bv    = (const float*)d_in[7];
    float* out = (float*)d_out;

    dim3 gA((B_ * S_) / 64, 3);
    proj_kernel<<<gA, 128>>>(query, value, Wq, bq, Wk, bk, Wv, bv);

    const int smem_bytes = (NB * KP + NB * 64 + TJ * 64 + TJ * 132) * (int)sizeof(float);
    cudaFuncSetAttribute(attn_kernel, cudaFuncAttributeMaxDynamicSharedMemorySize, smem_bytes);
    dim3 gB(S_ / TJ, B_);
    attn_kernel<<<gB, 512, smem_bytes>>>(out);
}